// round 8
// baseline (speedup 1.0000x reference)
#include <cuda_runtime.h>
#include <cuda_bf16.h>
#include <stdint.h>

#define S_REAL   308
#define SP       320     // padded state count
#define E_DIM    126
#define T_LEN    4096
#define NBATCH   32
#define NIP      160     // SP/2 pair-words of alpha
#define SCAN_THREADS 320

// Scratch (device globals — no allocation in kernel_launch)
__device__ __nv_bfloat16 g_emis[(size_t)NBATCH * T_LEN * SP];   // 80 MB
// A pair-words, column-per-thread: g_acol[ip*SP + j] = bf16x2(A[2ip][j],A[2ip+1][j])*128
__device__ uint32_t g_acol[160 * SP];                            // 200 KB

__device__ __forceinline__ __nv_bfloat162 u32_bf2(uint32_t v) {
    return *reinterpret_cast<__nv_bfloat162*>(&v);
}
__device__ __forceinline__ uint32_t bf2_u32(__nv_bfloat162 v) {
    return *reinterpret_cast<uint32_t*>(&v);
}

// ---------------------------------------------------------------------------
// Merged prep + emission GEMM. Blocks (bx==0, by<80) pack A*128 into g_acol,
// then all blocks run the emission GEMM tile. 2 launches per call total.
// ---------------------------------------------------------------------------
__global__ void __launch_bounds__(256)
prep_gemm_kernel(const float* __restrict__ inp, const float* __restrict__ Bm,
                 const float* __restrict__ A) {
    const int tid = threadIdx.x;

    if (blockIdx.x == 0 && blockIdx.y < 80) {
        int gt = blockIdx.y * 256 + tid;
        for (int wi = gt; wi < 160 * SP; wi += 80 * 256) {
            int ip = wi / SP;
            int j  = wi - ip * SP;
            int i0 = 2 * ip, i1 = i0 + 1;
            float a0 = (i0 < S_REAL && j < S_REAL) ? A[i0 * S_REAL + j] * 128.f : 0.f;
            float a1 = (i1 < S_REAL && j < S_REAL) ? A[i1 * S_REAL + j] * 128.f : 0.f;
            g_acol[wi] = bf2_u32(__floats2bfloat162_rn(a0, a1));
        }
    }

    // ---------------- GEMM part (all blocks) ----------------
    __shared__ uint32_t sAp[64][16];
    __shared__ uint32_t sBp[16][64];

    const int tx = tid & 15;
    const int ty = tid >> 4;
    const int n0 = blockIdx.x * 64;
    const int m0 = blockIdx.y * 64;

    float acc[4][4];
#pragma unroll
    for (int u = 0; u < 4; ++u)
#pragma unroll
        for (int v = 0; v < 4; ++v) acc[u][v] = 0.f;

    const __nv_bfloat162 zero2 = __floats2bfloat162_rn(0.f, 0.f);

    for (int k0 = 0; k0 < 128; k0 += 32) {
#pragma unroll
        for (int r = 0; r < 4; ++r) {
            int lin = tid + r * 256;
            int mm = lin >> 4, kp = lin & 15;
            int k = k0 + 2 * kp;
            __nv_bfloat162 w = zero2;
            if (k < E_DIM) {
                float2 f = *reinterpret_cast<const float2*>(
                    &inp[(size_t)(m0 + mm) * E_DIM + k]);
                w = __floats2bfloat162_rn(f.x, f.y);
            }
            sAp[mm][kp] = bf2_u32(w);
        }
#pragma unroll
        for (int r = 0; r < 4; ++r) {
            int lin = tid + r * 256;
            int kp = lin >> 6, n = lin & 63;
            int k = k0 + 2 * kp;
            int nn = n0 + n;
            __nv_bfloat162 w = zero2;
            if (k < E_DIM && nn < S_REAL) {
                float2 f = *reinterpret_cast<const float2*>(
                    &Bm[(size_t)nn * E_DIM + k]);
                w = __floats2bfloat162_rn(f.x, f.y);
            }
            sBp[kp][n] = bf2_u32(w);
        }
        __syncthreads();

        __nv_bfloat162 acc2[4][4];
#pragma unroll
        for (int u = 0; u < 4; ++u)
#pragma unroll
            for (int v = 0; v < 4; ++v) acc2[u][v] = zero2;

#pragma unroll
        for (int kp = 0; kp < 16; ++kp) {
            uint4 bv = *reinterpret_cast<const uint4*>(&sBp[kp][tx * 4]);
            uint32_t a0 = sAp[ty * 4 + 0][kp];
            uint32_t a1 = sAp[ty * 4 + 1][kp];
            uint32_t a2 = sAp[ty * 4 + 2][kp];
            uint32_t a3 = sAp[ty * 4 + 3][kp];
            __nv_bfloat162 b0 = u32_bf2(bv.x), b1 = u32_bf2(bv.y);
            __nv_bfloat162 b2 = u32_bf2(bv.z), b3 = u32_bf2(bv.w);
            acc2[0][0] = __hfma2(u32_bf2(a0), b0, acc2[0][0]);
            acc2[0][1] = __hfma2(u32_bf2(a0), b1, acc2[0][1]);
            acc2[0][2] = __hfma2(u32_bf2(a0), b2, acc2[0][2]);
            acc2[0][3] = __hfma2(u32_bf2(a0), b3, acc2[0][3]);
            acc2[1][0] = __hfma2(u32_bf2(a1), b0, acc2[1][0]);
            acc2[1][1] = __hfma2(u32_bf2(a1), b1, acc2[1][1]);
            acc2[1][2] = __hfma2(u32_bf2(a1), b2, acc2[1][2]);
            acc2[1][3] = __hfma2(u32_bf2(a1), b3, acc2[1][3]);
            acc2[2][0] = __hfma2(u32_bf2(a2), b0, acc2[2][0]);
            acc2[2][1] = __hfma2(u32_bf2(a2), b1, acc2[2][1]);
            acc2[2][2] = __hfma2(u32_bf2(a2), b2, acc2[2][2]);
            acc2[2][3] = __hfma2(u32_bf2(a2), b3, acc2[2][3]);
            acc2[3][0] = __hfma2(u32_bf2(a3), b0, acc2[3][0]);
            acc2[3][1] = __hfma2(u32_bf2(a3), b1, acc2[3][1]);
            acc2[3][2] = __hfma2(u32_bf2(a3), b2, acc2[3][2]);
            acc2[3][3] = __hfma2(u32_bf2(a3), b3, acc2[3][3]);
        }
#pragma unroll
        for (int u = 0; u < 4; ++u)
#pragma unroll
            for (int v = 0; v < 4; ++v) {
                float2 p = __bfloat1622float2(acc2[u][v]);
                acc[u][v] += p.x + p.y;
            }
        __syncthreads();
    }
#pragma unroll
    for (int u = 0; u < 4; ++u) {
        int m = m0 + ty * 4 + u;
        size_t base = (size_t)m * SP + n0 + tx * 4;
#pragma unroll
        for (int v = 0; v < 4; v += 2) {
            __nv_bfloat162 p = __floats2bfloat162_rn(acc[u][v], acc[u][v + 1]);
            *reinterpret_cast<uint32_t*>(&g_emis[base + v]) = bf2_u32(p);
        }
    }
}

// ---------------------------------------------------------------------------
// Scan: one CTA per batch, 320 threads, thread j owns output state j and the
// ENTIRE A column for j: 160 bf16x2 words register-resident (160 regs).
// Per step: 40 broadcast LDS.128 of alpha + 160 HFMA2 into 4 accumulators
// (40-term bf16 chains), collapse to fp32, multiply by emission, pack pairs,
// store to the other alpha buffer, ONE __syncthreads. A prescaled by 128;
// renormalize + log-accumulate every 16 steps; ll -= 4095*log(128).
// ---------------------------------------------------------------------------
__global__ void __launch_bounds__(SCAN_THREADS, 1)
scan_kernel(const float* __restrict__ Ivec, float* __restrict__ out) {
    __shared__ uint32_t s_alpha[2][NIP];   // bf16 alpha pairs, double-buffered
    __shared__ float    s_w[10];
    __shared__ float    s_inv;

    const int b    = blockIdx.x;
    const int tid  = threadIdx.x;          // = j
    const int wrp  = tid >> 5;
    const int lane = tid & 31;

    const __nv_bfloat16* erow = g_emis + (size_t)b * T_LEN * SP;

    // whole A column for state j: 160 words, coalesced (stride SP across ip)
    uint32_t rA[160];
#pragma unroll
    for (int ip = 0; ip < 160; ++ip) rA[ip] = g_acol[(size_t)ip * SP + tid];

    // t = 0: alpha0 = I * e0 (unnormalized, NOT prescaled) into buffer 1
    if (tid < NIP) {
        int j0 = 2 * tid, j1 = j0 + 1;
        float e0 = __bfloat162float(erow[j0]);
        float e1 = __bfloat162float(erow[j1]);
        float w0 = (j0 < S_REAL) ? Ivec[j0] : 0.f;
        float w1 = (j1 < S_REAL) ? Ivec[j1] : 0.f;
        s_alpha[1][tid] = bf2_u32(__floats2bfloat162_rn(w0 * e0, w1 * e1));
    }
    __syncthreads();

    float ll = 0.f;
    float e_cur = __bfloat162float(erow[(size_t)SP + tid]);

    const __nv_bfloat162 zero2 = __floats2bfloat162_rn(0.f, 0.f);

    for (int t = 1; t < T_LEN; ++t) {
        const int cur = t & 1;
        float e_next = 0.f;
        if (t + 1 < T_LEN)
            e_next = __bfloat162float(erow[(size_t)(t + 1) * SP + tid]);

        const uint4* al4 = reinterpret_cast<const uint4*>(s_alpha[cur]);

        __nv_bfloat162 ac0 = zero2, ac1 = zero2, ac2 = zero2, ac3 = zero2;

        // 40 chunks: broadcast-load 4 alpha words, 4 HFMA2 (one per accum)
#pragma unroll
        for (int c = 0; c < 40; ++c) {
            uint4 av = al4[c];
            ac0 = __hfma2(u32_bf2(rA[4 * c + 0]), u32_bf2(av.x), ac0);
            ac1 = __hfma2(u32_bf2(rA[4 * c + 1]), u32_bf2(av.y), ac1);
            ac2 = __hfma2(u32_bf2(rA[4 * c + 2]), u32_bf2(av.z), ac2);
            ac3 = __hfma2(u32_bf2(rA[4 * c + 3]), u32_bf2(av.w), ac3);
        }

        float2 p0 = __bfloat1622float2(ac0);
        float2 p1 = __bfloat1622float2(ac1);
        float2 p2 = __bfloat1622float2(ac2);
        float2 p3 = __bfloat1622float2(ac3);
        float f = ((p0.x + p0.y) + (p1.x + p1.y)) +
                  ((p2.x + p2.y) + (p3.x + p3.y));

        float o = f * e_cur;

        if ((t & 15) == 15) {
            // renormalize: full-warp reduce (32 distinct j), then 10-way combine
            float s = o;
#pragma unroll
            for (int off = 16; off > 0; off >>= 1)
                s += __shfl_xor_sync(0xffffffffu, s, off);
            if (lane == 0) s_w[wrp] = s;
            __syncthreads();
            if (tid == 0) {
                float z = 0.f;
#pragma unroll
                for (int k = 0; k < 10; ++k) z += s_w[k];
                ll += logf(z);
                s_inv = 1.0f / z;
            }
            __syncthreads();
            o *= s_inv;
        }

        // pack (j even, j odd) lane pair; even lane stores the word
        float op = __shfl_down_sync(0xffffffffu, o, 1);
        if ((lane & 1) == 0)
            s_alpha[cur ^ 1][tid >> 1] = bf2_u32(__floats2bfloat162_rn(o, op));
        __syncthreads();

        e_cur = e_next;
    }

    // each of the 4095 steps carried an extra factor 128 (folded into A)
    if (tid == 0) out[b] = ll - 4095.0f * logf(128.0f);
}

// ---------------------------------------------------------------------------
extern "C" void kernel_launch(void* const* d_in, const int* in_sizes, int n_in,
                              void* d_out, int out_size) {
    const float* inputs = nullptr;
    const float* A      = nullptr;
    const float* Bm     = nullptr;
    const float* Ivec   = nullptr;
    for (int i = 0; i < n_in; ++i) {
        switch (in_sizes[i]) {
            case NBATCH * T_LEN * E_DIM: inputs = (const float*)d_in[i]; break;
            case S_REAL * S_REAL:        A      = (const float*)d_in[i]; break;
            case S_REAL * E_DIM:         Bm     = (const float*)d_in[i]; break;
            case S_REAL:                 Ivec   = (const float*)d_in[i]; break;
            default: break;
        }
    }
    if (!inputs) inputs = (const float*)d_in[0];
    if (!A)      A      = (const float*)d_in[1];
    if (!Bm)     Bm     = (const float*)d_in[2];
    if (!Ivec)   Ivec   = (const float*)d_in[3];
    float* out = (float*)d_out;

    dim3 ggrid(SP / 64, (NBATCH * T_LEN) / 64);   // (5, 2048)
    prep_gemm_kernel<<<ggrid, 256>>>(inputs, Bm, A);

    scan_kernel<<<NBATCH, SCAN_THREADS>>>(Ivec, out);
    (void)out_size;
}

// round 9
// speedup vs baseline: 1.2509x; 1.2509x over previous
#include <cuda_runtime.h>
#include <cuda_bf16.h>
#include <stdint.h>

#define S_REAL   308
#define SP       320     // padded state count
#define E_DIM    126
#define T_LEN    4096
#define NBATCH   32
#define NIP      160     // SP/2 pair-words of alpha
#define SCAN_THREADS 320
#define QRES     32      // resident uint4 quads (ip 0..127)
#define QTOT     40      // total quads (ip 0..159)

// Scratch (device globals — no allocation in kernel_launch)
__device__ __nv_bfloat16 g_emis[(size_t)NBATCH * T_LEN * SP];   // 80 MB
// A pair-words as uint4 quads: quad q (i-pairs 4q..4q+3) for state j lives at
// uint4 index q*SP + j. Values prescaled by 128.
__device__ uint32_t g_aq[QTOT * SP * 4];                         // 200 KB

__device__ __forceinline__ __nv_bfloat162 u32_bf2(uint32_t v) {
    return *reinterpret_cast<__nv_bfloat162*>(&v);
}
__device__ __forceinline__ uint32_t bf2_u32(__nv_bfloat162 v) {
    return *reinterpret_cast<uint32_t*>(&v);
}

// ---------------------------------------------------------------------------
// Merged prep + emission GEMM. Blocks (bx==0, by<80) pack A*128 into g_aq,
// then all blocks run the emission GEMM tile. 2 launches per call total.
// ---------------------------------------------------------------------------
__global__ void __launch_bounds__(256)
prep_gemm_kernel(const float* __restrict__ inp, const float* __restrict__ Bm,
                 const float* __restrict__ A) {
    const int tid = threadIdx.x;

    if (blockIdx.x == 0 && blockIdx.y < 80) {
        int gt = blockIdx.y * 256 + tid;
        for (int wi = gt; wi < 160 * SP; wi += 80 * 256) {
            int ip = wi / SP;
            int j  = wi - ip * SP;
            int i0 = 2 * ip, i1 = i0 + 1;
            float a0 = (i0 < S_REAL && j < S_REAL) ? A[i0 * S_REAL + j] * 128.f : 0.f;
            float a1 = (i1 < S_REAL && j < S_REAL) ? A[i1 * S_REAL + j] * 128.f : 0.f;
            uint32_t word = bf2_u32(__floats2bfloat162_rn(a0, a1));
            g_aq[((ip >> 2) * SP + j) * 4 + (ip & 3)] = word;
        }
    }

    // ---------------- GEMM part (all blocks) ----------------
    __shared__ uint32_t sAp[64][16];
    __shared__ uint32_t sBp[16][64];

    const int tx = tid & 15;
    const int ty = tid >> 4;
    const int n0 = blockIdx.x * 64;
    const int m0 = blockIdx.y * 64;

    float acc[4][4];
#pragma unroll
    for (int u = 0; u < 4; ++u)
#pragma unroll
        for (int v = 0; v < 4; ++v) acc[u][v] = 0.f;

    const __nv_bfloat162 zero2 = __floats2bfloat162_rn(0.f, 0.f);

    for (int k0 = 0; k0 < 128; k0 += 32) {
#pragma unroll
        for (int r = 0; r < 4; ++r) {
            int lin = tid + r * 256;
            int mm = lin >> 4, kp = lin & 15;
            int k = k0 + 2 * kp;
            __nv_bfloat162 w = zero2;
            if (k < E_DIM) {
                float2 f = *reinterpret_cast<const float2*>(
                    &inp[(size_t)(m0 + mm) * E_DIM + k]);
                w = __floats2bfloat162_rn(f.x, f.y);
            }
            sAp[mm][kp] = bf2_u32(w);
        }
#pragma unroll
        for (int r = 0; r < 4; ++r) {
            int lin = tid + r * 256;
            int kp = lin >> 6, n = lin & 63;
            int k = k0 + 2 * kp;
            int nn = n0 + n;
            __nv_bfloat162 w = zero2;
            if (k < E_DIM && nn < S_REAL) {
                float2 f = *reinterpret_cast<const float2*>(
                    &Bm[(size_t)nn * E_DIM + k]);
                w = __floats2bfloat162_rn(f.x, f.y);
            }
            sBp[kp][n] = bf2_u32(w);
        }
        __syncthreads();

        __nv_bfloat162 acc2[4][4];
#pragma unroll
        for (int u = 0; u < 4; ++u)
#pragma unroll
            for (int v = 0; v < 4; ++v) acc2[u][v] = zero2;

#pragma unroll
        for (int kp = 0; kp < 16; ++kp) {
            uint4 bv = *reinterpret_cast<const uint4*>(&sBp[kp][tx * 4]);
            uint32_t a0 = sAp[ty * 4 + 0][kp];
            uint32_t a1 = sAp[ty * 4 + 1][kp];
            uint32_t a2 = sAp[ty * 4 + 2][kp];
            uint32_t a3 = sAp[ty * 4 + 3][kp];
            __nv_bfloat162 b0 = u32_bf2(bv.x), b1 = u32_bf2(bv.y);
            __nv_bfloat162 b2 = u32_bf2(bv.z), b3 = u32_bf2(bv.w);
            acc2[0][0] = __hfma2(u32_bf2(a0), b0, acc2[0][0]);
            acc2[0][1] = __hfma2(u32_bf2(a0), b1, acc2[0][1]);
            acc2[0][2] = __hfma2(u32_bf2(a0), b2, acc2[0][2]);
            acc2[0][3] = __hfma2(u32_bf2(a0), b3, acc2[0][3]);
            acc2[1][0] = __hfma2(u32_bf2(a1), b0, acc2[1][0]);
            acc2[1][1] = __hfma2(u32_bf2(a1), b1, acc2[1][1]);
            acc2[1][2] = __hfma2(u32_bf2(a1), b2, acc2[1][2]);
            acc2[1][3] = __hfma2(u32_bf2(a1), b3, acc2[1][3]);
            acc2[2][0] = __hfma2(u32_bf2(a2), b0, acc2[2][0]);
            acc2[2][1] = __hfma2(u32_bf2(a2), b1, acc2[2][1]);
            acc2[2][2] = __hfma2(u32_bf2(a2), b2, acc2[2][2]);
            acc2[2][3] = __hfma2(u32_bf2(a2), b3, acc2[2][3]);
            acc2[3][0] = __hfma2(u32_bf2(a3), b0, acc2[3][0]);
            acc2[3][1] = __hfma2(u32_bf2(a3), b1, acc2[3][1]);
            acc2[3][2] = __hfma2(u32_bf2(a3), b2, acc2[3][2]);
            acc2[3][3] = __hfma2(u32_bf2(a3), b3, acc2[3][3]);
        }
#pragma unroll
        for (int u = 0; u < 4; ++u)
#pragma unroll
            for (int v = 0; v < 4; ++v) {
                float2 p = __bfloat1622float2(acc2[u][v]);
                acc[u][v] += p.x + p.y;
            }
        __syncthreads();
    }
#pragma unroll
    for (int u = 0; u < 4; ++u) {
        int m = m0 + ty * 4 + u;
        size_t base = (size_t)m * SP + n0 + tx * 4;
#pragma unroll
        for (int v = 0; v < 4; v += 2) {
            __nv_bfloat162 p = __floats2bfloat162_rn(acc[u][v], acc[u][v + 1]);
            *reinterpret_cast<uint32_t*>(&g_emis[base + v]) = bf2_u32(p);
        }
    }
}

// ---------------------------------------------------------------------------
// Scan: one CTA per batch, 320 threads, thread j owns output state j.
// A column for j: 32 quads (128 words) register-resident, 8 quads streamed
// per step as coalesced LDG.128 in two staggered waves (L1-hot, 320 wf/step).
// Per step: 40 broadcast LDS.128 of alpha + 160 HFMA2 into 4 accumulators,
// fp32 collapse, emission multiply, pair-pack via shfl, store to the other
// alpha buffer, ONE __syncthreads. A prescaled by 128; renormalize +
// log-accumulate every 16 steps; ll -= 4095*log(128).
// ---------------------------------------------------------------------------
__global__ void __launch_bounds__(SCAN_THREADS, 1)
scan_kernel(const float* __restrict__ Ivec, float* __restrict__ out) {
    __shared__ uint32_t s_alpha[2][NIP];   // bf16 alpha pairs, double-buffered
    __shared__ float    s_w[10];
    __shared__ float    s_inv;

    const int b    = blockIdx.x;
    const int tid  = threadIdx.x;          // = j
    const int wrp  = tid >> 5;
    const int lane = tid & 31;

    const __nv_bfloat16* erow = g_emis + (size_t)b * T_LEN * SP;
    const uint4* Aq = reinterpret_cast<const uint4*>(g_aq) + tid;

    // resident A: quads 0..31 (i-pairs 0..127), 128 registers
    uint4 rA[QRES];
#pragma unroll
    for (int q = 0; q < QRES; ++q) rA[q] = Aq[q * SP];

    // t = 0: alpha0 = I * e0 (unnormalized, NOT prescaled) into buffer 1
    if (tid < NIP) {
        int j0 = 2 * tid, j1 = j0 + 1;
        float e0 = __bfloat162float(erow[j0]);
        float e1 = __bfloat162float(erow[j1]);
        float w0 = (j0 < S_REAL) ? Ivec[j0] : 0.f;
        float w1 = (j1 < S_REAL) ? Ivec[j1] : 0.f;
        s_alpha[1][tid] = bf2_u32(__floats2bfloat162_rn(w0 * e0, w1 * e1));
    }
    __syncthreads();

    float ll = 0.f;
    float e_cur = __bfloat162float(erow[(size_t)SP + tid]);

    const __nv_bfloat162 zero2 = __floats2bfloat162_rn(0.f, 0.f);

    for (int t = 1; t < T_LEN; ++t) {
        const int cur = t & 1;
        float e_next = 0.f;
        if (t + 1 < T_LEN)
            e_next = __bfloat162float(erow[(size_t)(t + 1) * SP + tid]);

        const uint4* al4 = reinterpret_cast<const uint4*>(s_alpha[cur]);

        __nv_bfloat162 ac0 = zero2, ac1 = zero2, ac2 = zero2, ac3 = zero2;

        // streamed wave 1: quads 32..35 (issued before resident math)
        uint4 sA0 = Aq[32 * SP];
        uint4 sA1 = Aq[33 * SP];
        uint4 sA2 = Aq[34 * SP];
        uint4 sA3 = Aq[35 * SP];

        // resident quads 0..15
#pragma unroll
        for (int c = 0; c < 16; ++c) {
            uint4 av = al4[c];
            ac0 = __hfma2(u32_bf2(rA[c].x), u32_bf2(av.x), ac0);
            ac1 = __hfma2(u32_bf2(rA[c].y), u32_bf2(av.y), ac1);
            ac2 = __hfma2(u32_bf2(rA[c].z), u32_bf2(av.z), ac2);
            ac3 = __hfma2(u32_bf2(rA[c].w), u32_bf2(av.w), ac3);
        }

        // streamed wave 2: quads 36..39
        uint4 sB0 = Aq[36 * SP];
        uint4 sB1 = Aq[37 * SP];
        uint4 sB2 = Aq[38 * SP];
        uint4 sB3 = Aq[39 * SP];

        // resident quads 16..31
#pragma unroll
        for (int c = 16; c < 32; ++c) {
            uint4 av = al4[c];
            ac0 = __hfma2(u32_bf2(rA[c].x), u32_bf2(av.x), ac0);
            ac1 = __hfma2(u32_bf2(rA[c].y), u32_bf2(av.y), ac1);
            ac2 = __hfma2(u32_bf2(rA[c].z), u32_bf2(av.z), ac2);
            ac3 = __hfma2(u32_bf2(rA[c].w), u32_bf2(av.w), ac3);
        }

        // streamed quads 32..39
        {
            uint4 av;
            av = al4[32];
            ac0 = __hfma2(u32_bf2(sA0.x), u32_bf2(av.x), ac0);
            ac1 = __hfma2(u32_bf2(sA0.y), u32_bf2(av.y), ac1);
            ac2 = __hfma2(u32_bf2(sA0.z), u32_bf2(av.z), ac2);
            ac3 = __hfma2(u32_bf2(sA0.w), u32_bf2(av.w), ac3);
            av = al4[33];
            ac0 = __hfma2(u32_bf2(sA1.x), u32_bf2(av.x), ac0);
            ac1 = __hfma2(u32_bf2(sA1.y), u32_bf2(av.y), ac1);
            ac2 = __hfma2(u32_bf2(sA1.z), u32_bf2(av.z), ac2);
            ac3 = __hfma2(u32_bf2(sA1.w), u32_bf2(av.w), ac3);
            av = al4[34];
            ac0 = __hfma2(u32_bf2(sA2.x), u32_bf2(av.x), ac0);
            ac1 = __hfma2(u32_bf2(sA2.y), u32_bf2(av.y), ac1);
            ac2 = __hfma2(u32_bf2(sA2.z), u32_bf2(av.z), ac2);
            ac3 = __hfma2(u32_bf2(sA2.w), u32_bf2(av.w), ac3);
            av = al4[35];
            ac0 = __hfma2(u32_bf2(sA3.x), u32_bf2(av.x), ac0);
            ac1 = __hfma2(u32_bf2(sA3.y), u32_bf2(av.y), ac1);
            ac2 = __hfma2(u32_bf2(sA3.z), u32_bf2(av.z), ac2);
            ac3 = __hfma2(u32_bf2(sA3.w), u32_bf2(av.w), ac3);
            av = al4[36];
            ac0 = __hfma2(u32_bf2(sB0.x), u32_bf2(av.x), ac0);
            ac1 = __hfma2(u32_bf2(sB0.y), u32_bf2(av.y), ac1);
            ac2 = __hfma2(u32_bf2(sB0.z), u32_bf2(av.z), ac2);
            ac3 = __hfma2(u32_bf2(sB0.w), u32_bf2(av.w), ac3);
            av = al4[37];
            ac0 = __hfma2(u32_bf2(sB1.x), u32_bf2(av.x), ac0);
            ac1 = __hfma2(u32_bf2(sB1.y), u32_bf2(av.y), ac1);
            ac2 = __hfma2(u32_bf2(sB1.z), u32_bf2(av.z), ac2);
            ac3 = __hfma2(u32_bf2(sB1.w), u32_bf2(av.w), ac3);
            av = al4[38];
            ac0 = __hfma2(u32_bf2(sB2.x), u32_bf2(av.x), ac0);
            ac1 = __hfma2(u32_bf2(sB2.y), u32_bf2(av.y), ac1);
            ac2 = __hfma2(u32_bf2(sB2.z), u32_bf2(av.z), ac2);
            ac3 = __hfma2(u32_bf2(sB2.w), u32_bf2(av.w), ac3);
            av = al4[39];
            ac0 = __hfma2(u32_bf2(sB3.x), u32_bf2(av.x), ac0);
            ac1 = __hfma2(u32_bf2(sB3.y), u32_bf2(av.y), ac1);
            ac2 = __hfma2(u32_bf2(sB3.z), u32_bf2(av.z), ac2);
            ac3 = __hfma2(u32_bf2(sB3.w), u32_bf2(av.w), ac3);
        }

        float2 p0 = __bfloat1622float2(ac0);
        float2 p1 = __bfloat1622float2(ac1);
        float2 p2 = __bfloat1622float2(ac2);
        float2 p3 = __bfloat1622float2(ac3);
        float f = ((p0.x + p0.y) + (p1.x + p1.y)) +
                  ((p2.x + p2.y) + (p3.x + p3.y));

        float o = f * e_cur;

        if ((t & 15) == 15) {
            // renormalize: full-warp reduce (32 distinct j), then 10-way combine
            float s = o;
#pragma unroll
            for (int off = 16; off > 0; off >>= 1)
                s += __shfl_xor_sync(0xffffffffu, s, off);
            if (lane == 0) s_w[wrp] = s;
            __syncthreads();
            if (tid == 0) {
                float z = 0.f;
#pragma unroll
                for (int k = 0; k < 10; ++k) z += s_w[k];
                ll += logf(z);
                s_inv = 1.0f / z;
            }
            __syncthreads();
            o *= s_inv;
        }

        // pack (j even, j odd) lane pair; even lane stores the word
        float op = __shfl_down_sync(0xffffffffu, o, 1);
        if ((lane & 1) == 0)
            s_alpha[cur ^ 1][tid >> 1] = bf2_u32(__floats2bfloat162_rn(o, op));
        __syncthreads();

        e_cur = e_next;
    }

    // each of the 4095 steps carried an extra factor 128 (folded into A)
    if (tid == 0) out[b] = ll - 4095.0f * logf(128.0f);
}

// ---------------------------------------------------------------------------
extern "C" void kernel_launch(void* const* d_in, const int* in_sizes, int n_in,
                              void* d_out, int out_size) {
    const float* inputs = nullptr;
    const float* A      = nullptr;
    const float* Bm     = nullptr;
    const float* Ivec   = nullptr;
    for (int i = 0; i < n_in; ++i) {
        switch (in_sizes[i]) {
            case NBATCH * T_LEN * E_DIM: inputs = (const float*)d_in[i]; break;
            case S_REAL * S_REAL:        A      = (const float*)d_in[i]; break;
            case S_REAL * E_DIM:         Bm     = (const float*)d_in[i]; break;
            case S_REAL:                 Ivec   = (const float*)d_in[i]; break;
            default: break;
        }
    }
    if (!inputs) inputs = (const float*)d_in[0];
    if (!A)      A      = (const float*)d_in[1];
    if (!Bm)     Bm     = (const float*)d_in[2];
    if (!Ivec)   Ivec   = (const float*)d_in[3];
    float* out = (float*)d_out;

    dim3 ggrid(SP / 64, (NBATCH * T_LEN) / 64);   // (5, 2048)
    prep_gemm_kernel<<<ggrid, 256>>>(inputs, Bm, A);

    scan_kernel<<<NBATCH, SCAN_THREADS>>>(Ivec, out);
    (void)out_size;
}

// round 10
// speedup vs baseline: 1.2583x; 1.0059x over previous
#include <cuda_runtime.h>
#include <cuda_bf16.h>
#include <stdint.h>

#define S_REAL   308
#define SP       320     // padded state count
#define E_DIM    126
#define T_LEN    4096
#define NBATCH   32
#define NIP      160     // SP/2 pair-words of alpha
#define SCAN_THREADS 640

// Scratch (device globals — no allocation in kernel_launch)
__device__ __nv_bfloat16 g_emis[(size_t)NBATCH * T_LEN * SP];   // 80 MB
// A pair-words, thread-major: uint4 chunk q (i-pairs h*80+4q..4q+3 for thread
// g = 2j+h) lives at uint4 index q*640 + g. Prescaled by 128.
__device__ uint32_t g_apk2[640 * 80];                            // 200 KB

__device__ __forceinline__ __nv_bfloat162 u32_bf2(uint32_t v) {
    return *reinterpret_cast<__nv_bfloat162*>(&v);
}
__device__ __forceinline__ uint32_t bf2_u32(__nv_bfloat162 v) {
    return *reinterpret_cast<uint32_t*>(&v);
}

// ---------------------------------------------------------------------------
// Merged prep + emission GEMM. Blocks (bx==0, by<80) pack A*128 into g_apk2,
// then all blocks run the emission GEMM tile. 2 launches per call total.
// ---------------------------------------------------------------------------
__global__ void __launch_bounds__(256)
prep_gemm_kernel(const float* __restrict__ inp, const float* __restrict__ Bm,
                 const float* __restrict__ A) {
    const int tid = threadIdx.x;

    if (blockIdx.x == 0 && blockIdx.y < 80) {
        int gt = blockIdx.y * 256 + tid;
        for (int wi = gt; wi < 160 * SP; wi += 80 * 256) {
            int ip = wi / SP;
            int j  = wi - ip * SP;
            int i0 = 2 * ip, i1 = i0 + 1;
            float a0 = (i0 < S_REAL && j < S_REAL) ? A[i0 * S_REAL + j] * 128.f : 0.f;
            float a1 = (i1 < S_REAL && j < S_REAL) ? A[i1 * S_REAL + j] * 128.f : 0.f;
            uint32_t word = bf2_u32(__floats2bfloat162_rn(a0, a1));
            int h = ip / 80, kk = ip - h * 80;
            int g = 2 * j + h;
            g_apk2[((kk >> 2) * 640 + g) * 4 + (kk & 3)] = word;
        }
    }

    // ---------------- GEMM part (all blocks) ----------------
    __shared__ uint32_t sAp[64][16];
    __shared__ uint32_t sBp[16][64];

    const int tx = tid & 15;
    const int ty = tid >> 4;
    const int n0 = blockIdx.x * 64;
    const int m0 = blockIdx.y * 64;

    float acc[4][4];
#pragma unroll
    for (int u = 0; u < 4; ++u)
#pragma unroll
        for (int v = 0; v < 4; ++v) acc[u][v] = 0.f;

    const __nv_bfloat162 zero2 = __floats2bfloat162_rn(0.f, 0.f);

    for (int k0 = 0; k0 < 128; k0 += 32) {
#pragma unroll
        for (int r = 0; r < 4; ++r) {
            int lin = tid + r * 256;
            int mm = lin >> 4, kp = lin & 15;
            int k = k0 + 2 * kp;
            __nv_bfloat162 w = zero2;
            if (k < E_DIM) {
                float2 f = *reinterpret_cast<const float2*>(
                    &inp[(size_t)(m0 + mm) * E_DIM + k]);
                w = __floats2bfloat162_rn(f.x, f.y);
            }
            sAp[mm][kp] = bf2_u32(w);
        }
#pragma unroll
        for (int r = 0; r < 4; ++r) {
            int lin = tid + r * 256;
            int kp = lin >> 6, n = lin & 63;
            int k = k0 + 2 * kp;
            int nn = n0 + n;
            __nv_bfloat162 w = zero2;
            if (k < E_DIM && nn < S_REAL) {
                float2 f = *reinterpret_cast<const float2*>(
                    &Bm[(size_t)nn * E_DIM + k]);
                w = __floats2bfloat162_rn(f.x, f.y);
            }
            sBp[kp][n] = bf2_u32(w);
        }
        __syncthreads();

        __nv_bfloat162 acc2[4][4];
#pragma unroll
        for (int u = 0; u < 4; ++u)
#pragma unroll
            for (int v = 0; v < 4; ++v) acc2[u][v] = zero2;

#pragma unroll
        for (int kp = 0; kp < 16; ++kp) {
            uint4 bv = *reinterpret_cast<const uint4*>(&sBp[kp][tx * 4]);
            uint32_t a0 = sAp[ty * 4 + 0][kp];
            uint32_t a1 = sAp[ty * 4 + 1][kp];
            uint32_t a2 = sAp[ty * 4 + 2][kp];
            uint32_t a3 = sAp[ty * 4 + 3][kp];
            __nv_bfloat162 b0 = u32_bf2(bv.x), b1 = u32_bf2(bv.y);
            __nv_bfloat162 b2 = u32_bf2(bv.z), b3 = u32_bf2(bv.w);
            acc2[0][0] = __hfma2(u32_bf2(a0), b0, acc2[0][0]);
            acc2[0][1] = __hfma2(u32_bf2(a0), b1, acc2[0][1]);
            acc2[0][2] = __hfma2(u32_bf2(a0), b2, acc2[0][2]);
            acc2[0][3] = __hfma2(u32_bf2(a0), b3, acc2[0][3]);
            acc2[1][0] = __hfma2(u32_bf2(a1), b0, acc2[1][0]);
            acc2[1][1] = __hfma2(u32_bf2(a1), b1, acc2[1][1]);
            acc2[1][2] = __hfma2(u32_bf2(a1), b2, acc2[1][2]);
            acc2[1][3] = __hfma2(u32_bf2(a1), b3, acc2[1][3]);
            acc2[2][0] = __hfma2(u32_bf2(a2), b0, acc2[2][0]);
            acc2[2][1] = __hfma2(u32_bf2(a2), b1, acc2[2][1]);
            acc2[2][2] = __hfma2(u32_bf2(a2), b2, acc2[2][2]);
            acc2[2][3] = __hfma2(u32_bf2(a2), b3, acc2[2][3]);
            acc2[3][0] = __hfma2(u32_bf2(a3), b0, acc2[3][0]);
            acc2[3][1] = __hfma2(u32_bf2(a3), b1, acc2[3][1]);
            acc2[3][2] = __hfma2(u32_bf2(a3), b2, acc2[3][2]);
            acc2[3][3] = __hfma2(u32_bf2(a3), b3, acc2[3][3]);
        }
#pragma unroll
        for (int u = 0; u < 4; ++u)
#pragma unroll
            for (int v = 0; v < 4; ++v) {
                float2 p = __bfloat1622float2(acc2[u][v]);
                acc[u][v] += p.x + p.y;
            }
        __syncthreads();
    }
#pragma unroll
    for (int u = 0; u < 4; ++u) {
        int m = m0 + ty * 4 + u;
        size_t base = (size_t)m * SP + n0 + tx * 4;
#pragma unroll
        for (int v = 0; v < 4; v += 2) {
            __nv_bfloat162 p = __floats2bfloat162_rn(acc[u][v], acc[u][v + 1]);
            *reinterpret_cast<uint32_t*>(&g_emis[base + v]) = bf2_u32(p);
        }
    }
}

// ---------------------------------------------------------------------------
// Scan: one CTA per batch, 640 threads (20 warps). Thread g: j = g>>1,
// h = g&1; computes the h-half (80 i-pairs) of alpha_new[j]. 14 A-quads
// register-resident (56 regs), 6 streamed in 3 staggered waves of 2 LDG.128.
// Alpha quads loaded singly in the fma loop (live ~2). Lane-pair combine via
// shfl_xor(1); pack via shfl_down(2); ONE __syncthreads per step.
// A prescaled by 128; renorm + log every 16 steps; ll -= 4095*log(128).
// ---------------------------------------------------------------------------
__global__ void __launch_bounds__(SCAN_THREADS, 1)
scan_kernel(const float* __restrict__ Ivec, float* __restrict__ out) {
    __shared__ uint32_t s_alpha[2][NIP];   // bf16 alpha pairs, double-buffered
    __shared__ float    s_w[20];
    __shared__ float    s_inv;

    const int b    = blockIdx.x;
    const int tid  = threadIdx.x;
    const int g    = tid;
    const int j    = g >> 1;
    const int h    = g & 1;
    const int wrp  = tid >> 5;
    const int lane = tid & 31;

    const __nv_bfloat16* erow = g_emis + (size_t)b * T_LEN * SP;
    const uint4* As = reinterpret_cast<const uint4*>(g_apk2) + g;

    // register-resident A: quads 0..13 (56 regs)
    uint4 rA[14];
#pragma unroll
    for (int r = 0; r < 14; ++r) rA[r] = As[r * 640];

    // t = 0: alpha0 = I * e0 (unnormalized) into buffer 1 (t=1 reads buf 1)
    if (tid < NIP) {
        int j0 = 2 * tid, j1 = j0 + 1;
        float e0 = __bfloat162float(erow[j0]);
        float e1 = __bfloat162float(erow[j1]);
        float w0 = (j0 < S_REAL) ? Ivec[j0] : 0.f;
        float w1 = (j1 < S_REAL) ? Ivec[j1] : 0.f;
        s_alpha[1][tid] = bf2_u32(__floats2bfloat162_rn(w0 * e0, w1 * e1));
    }
    __syncthreads();

    float ll = 0.f;
    float e_cur = __bfloat162float(erow[(size_t)SP + j]);

    const __nv_bfloat162 zero2 = __floats2bfloat162_rn(0.f, 0.f);

    for (int t = 1; t < T_LEN; ++t) {
        const int cur = t & 1;
        float e_next = 0.f;
        if (t + 1 < T_LEN)
            e_next = __bfloat162float(erow[(size_t)(t + 1) * SP + j]);

        const uint4* al4 = reinterpret_cast<const uint4*>(s_alpha[cur]) + h * 20;

        __nv_bfloat162 ac0 = zero2, ac1 = zero2;

        // wave 1: streamed quads 14,15
        uint4 s0 = As[14 * 640];
        uint4 s1 = As[15 * 640];

        // resident quads 0..6
#pragma unroll
        for (int q = 0; q < 7; ++q) {
            uint4 av = al4[q];
            uint4 w  = rA[q];
            ac0 = __hfma2(u32_bf2(w.x), u32_bf2(av.x), ac0);
            ac1 = __hfma2(u32_bf2(w.y), u32_bf2(av.y), ac1);
            ac0 = __hfma2(u32_bf2(w.z), u32_bf2(av.z), ac0);
            ac1 = __hfma2(u32_bf2(w.w), u32_bf2(av.w), ac1);
        }

        // wave 2: streamed quads 16,17
        uint4 s2 = As[16 * 640];
        uint4 s3 = As[17 * 640];

        // resident quads 7..13
#pragma unroll
        for (int q = 7; q < 14; ++q) {
            uint4 av = al4[q];
            uint4 w  = rA[q];
            ac0 = __hfma2(u32_bf2(w.x), u32_bf2(av.x), ac0);
            ac1 = __hfma2(u32_bf2(w.y), u32_bf2(av.y), ac1);
            ac0 = __hfma2(u32_bf2(w.z), u32_bf2(av.z), ac0);
            ac1 = __hfma2(u32_bf2(w.w), u32_bf2(av.w), ac1);
        }

        // consume wave 1 (quads 14,15)
        {
            uint4 av = al4[14];
            ac0 = __hfma2(u32_bf2(s0.x), u32_bf2(av.x), ac0);
            ac1 = __hfma2(u32_bf2(s0.y), u32_bf2(av.y), ac1);
            ac0 = __hfma2(u32_bf2(s0.z), u32_bf2(av.z), ac0);
            ac1 = __hfma2(u32_bf2(s0.w), u32_bf2(av.w), ac1);
            av = al4[15];
            ac0 = __hfma2(u32_bf2(s1.x), u32_bf2(av.x), ac0);
            ac1 = __hfma2(u32_bf2(s1.y), u32_bf2(av.y), ac1);
            ac0 = __hfma2(u32_bf2(s1.z), u32_bf2(av.z), ac0);
            ac1 = __hfma2(u32_bf2(s1.w), u32_bf2(av.w), ac1);
        }

        // wave 3: streamed quads 18,19
        uint4 s4 = As[18 * 640];
        uint4 s5 = As[19 * 640];

        // consume wave 2 (quads 16,17)
        {
            uint4 av = al4[16];
            ac0 = __hfma2(u32_bf2(s2.x), u32_bf2(av.x), ac0);
            ac1 = __hfma2(u32_bf2(s2.y), u32_bf2(av.y), ac1);
            ac0 = __hfma2(u32_bf2(s2.z), u32_bf2(av.z), ac0);
            ac1 = __hfma2(u32_bf2(s2.w), u32_bf2(av.w), ac1);
            av = al4[17];
            ac0 = __hfma2(u32_bf2(s3.x), u32_bf2(av.x), ac0);
            ac1 = __hfma2(u32_bf2(s3.y), u32_bf2(av.y), ac1);
            ac0 = __hfma2(u32_bf2(s3.z), u32_bf2(av.z), ac0);
            ac1 = __hfma2(u32_bf2(s3.w), u32_bf2(av.w), ac1);
        }
        // consume wave 3 (quads 18,19)
        {
            uint4 av = al4[18];
            ac0 = __hfma2(u32_bf2(s4.x), u32_bf2(av.x), ac0);
            ac1 = __hfma2(u32_bf2(s4.y), u32_bf2(av.y), ac1);
            ac0 = __hfma2(u32_bf2(s4.z), u32_bf2(av.z), ac0);
            ac1 = __hfma2(u32_bf2(s4.w), u32_bf2(av.w), ac1);
            av = al4[19];
            ac0 = __hfma2(u32_bf2(s5.x), u32_bf2(av.x), ac0);
            ac1 = __hfma2(u32_bf2(s5.y), u32_bf2(av.y), ac1);
            ac0 = __hfma2(u32_bf2(s5.z), u32_bf2(av.z), ac0);
            ac1 = __hfma2(u32_bf2(s5.w), u32_bf2(av.w), ac1);
        }

        float2 pa = __bfloat1622float2(ac0);
        float2 pb = __bfloat1622float2(ac1);
        float f = (pa.x + pa.y) + (pb.x + pb.y);

        // combine lane pair (h=0 + h=1 halves), apply emission
        float o = (f + __shfl_xor_sync(0xffffffffu, f, 1)) * e_cur;

        if ((t & 15) == 15) {
            // renormalize: offsets {2,4,8,16} sum 16 distinct j per warp
            float s = o;
            s += __shfl_xor_sync(0xffffffffu, s, 2);
            s += __shfl_xor_sync(0xffffffffu, s, 4);
            s += __shfl_xor_sync(0xffffffffu, s, 8);
            s += __shfl_xor_sync(0xffffffffu, s, 16);
            if (lane == 0) s_w[wrp] = s;
            __syncthreads();
            if (tid == 0) {
                float z = 0.f;
#pragma unroll
                for (int k = 0; k < 20; ++k) z += s_w[k];
                ll += logf(z);
                s_inv = 1.0f / z;
            }
            __syncthreads();
            o *= s_inv;
        }

        // pack (j even, j odd) = lanes l, l+2 at l%4==0; store next alpha
        float op = __shfl_down_sync(0xffffffffu, o, 2);
        if ((lane & 3) == 0)
            s_alpha[cur ^ 1][8 * wrp + (lane >> 2)] =
                bf2_u32(__floats2bfloat162_rn(o, op));
        __syncthreads();

        e_cur = e_next;
    }

    // each of the 4095 steps carried an extra factor 128 (folded into A)
    if (tid == 0) out[b] = ll - 4095.0f * logf(128.0f);
}

// ---------------------------------------------------------------------------
extern "C" void kernel_launch(void* const* d_in, const int* in_sizes, int n_in,
                              void* d_out, int out_size) {
    const float* inputs = nullptr;
    const float* A      = nullptr;
    const float* Bm     = nullptr;
    const float* Ivec   = nullptr;
    for (int i = 0; i < n_in; ++i) {
        switch (in_sizes[i]) {
            case NBATCH * T_LEN * E_DIM: inputs = (const float*)d_in[i]; break;
            case S_REAL * S_REAL:        A      = (const float*)d_in[i]; break;
            case S_REAL * E_DIM:         Bm     = (const float*)d_in[i]; break;
            case S_REAL:                 Ivec   = (const float*)d_in[i]; break;
            default: break;
        }
    }
    if (!inputs) inputs = (const float*)d_in[0];
    if (!A)      A      = (const float*)d_in[1];
    if (!Bm)     Bm     = (const float*)d_in[2];
    if (!Ivec)   Ivec   = (const float*)d_in[3];
    float* out = (float*)d_out;

    dim3 ggrid(SP / 64, (NBATCH * T_LEN) / 64);   // (5, 2048)
    prep_gemm_kernel<<<ggrid, 256>>>(inputs, Bm, A);

    scan_kernel<<<NBATCH, SCAN_THREADS>>>(Ivec, out);
    (void)out_size;
}

// round 11
// speedup vs baseline: 1.9111x; 1.5189x over previous
#include <cuda_runtime.h>
#include <cuda_bf16.h>
#include <stdint.h>

#define S_REAL   308
#define SP       320     // padded state count
#define E_DIM    126
#define T_LEN    4096
#define NBATCH   32
#define NIP      160     // SP/2 pair-words of alpha
#define SCAN_THREADS 512

// Scratch (device globals — no allocation in kernel_launch)
__device__ __nv_bfloat16 g_emis[(size_t)NBATCH * T_LEN * SP];   // 80 MB
// A pair-words for the 512-thread scan. Thread (ig = tid>>6, jj = tid&63)
// owns i-pairs ip = ig*20 + ql*4 + s (ql=0..4, s=0..3) for columns
// j = jj + 64*c (c=0..4). uint4 (ql,c) for thread lives at uint4 index
// ((ig*5+ql)*5 + c)*64 + jj  -> warp reads 512B coalesced. Prescaled x128.
__device__ uint32_t g_a[8 * 5 * 5 * 64 * 4];                     // 200 KB

__device__ __forceinline__ __nv_bfloat162 u32_bf2(uint32_t v) {
    return *reinterpret_cast<__nv_bfloat162*>(&v);
}
__device__ __forceinline__ uint32_t bf2_u32(__nv_bfloat162 v) {
    return *reinterpret_cast<uint32_t*>(&v);
}

// ---------------------------------------------------------------------------
// Merged prep + emission GEMM. Blocks (bx==0, by<80) pack A*128 into g_a,
// then all blocks run the emission GEMM tile. 2 launches per call total.
// ---------------------------------------------------------------------------
__global__ void __launch_bounds__(256)
prep_gemm_kernel(const float* __restrict__ inp, const float* __restrict__ Bm,
                 const float* __restrict__ A) {
    const int tid = threadIdx.x;

    if (blockIdx.x == 0 && blockIdx.y < 80) {
        int gt = blockIdx.y * 256 + tid;
        for (int wi = gt; wi < 160 * SP; wi += 80 * 256) {
            int ip = wi / SP;
            int j  = wi - ip * SP;
            int i0 = 2 * ip, i1 = i0 + 1;
            float a0 = (i0 < S_REAL && j < S_REAL) ? A[i0 * S_REAL + j] * 128.f : 0.f;
            float a1 = (i1 < S_REAL && j < S_REAL) ? A[i1 * S_REAL + j] * 128.f : 0.f;
            uint32_t word = bf2_u32(__floats2bfloat162_rn(a0, a1));
            int ig = ip / 20, r = ip % 20, ql = r >> 2, s = r & 3;
            int c = j >> 6, jj = j & 63;
            g_a[((((ig * 5 + ql) * 5 + c) * 64) + jj) * 4 + s] = word;
        }
    }

    // ---------------- GEMM part (all blocks) ----------------
    __shared__ uint32_t sAp[64][16];
    __shared__ uint32_t sBp[16][64];

    const int tx = tid & 15;
    const int ty = tid >> 4;
    const int n0 = blockIdx.x * 64;
    const int m0 = blockIdx.y * 64;

    float acc[4][4];
#pragma unroll
    for (int u = 0; u < 4; ++u)
#pragma unroll
        for (int v = 0; v < 4; ++v) acc[u][v] = 0.f;

    const __nv_bfloat162 zero2 = __floats2bfloat162_rn(0.f, 0.f);

    for (int k0 = 0; k0 < 128; k0 += 32) {
#pragma unroll
        for (int r = 0; r < 4; ++r) {
            int lin = tid + r * 256;
            int mm = lin >> 4, kp = lin & 15;
            int k = k0 + 2 * kp;
            __nv_bfloat162 w = zero2;
            if (k < E_DIM) {
                float2 f = *reinterpret_cast<const float2*>(
                    &inp[(size_t)(m0 + mm) * E_DIM + k]);
                w = __floats2bfloat162_rn(f.x, f.y);
            }
            sAp[mm][kp] = bf2_u32(w);
        }
#pragma unroll
        for (int r = 0; r < 4; ++r) {
            int lin = tid + r * 256;
            int kp = lin >> 6, n = lin & 63;
            int k = k0 + 2 * kp;
            int nn = n0 + n;
            __nv_bfloat162 w = zero2;
            if (k < E_DIM && nn < S_REAL) {
                float2 f = *reinterpret_cast<const float2*>(
                    &Bm[(size_t)nn * E_DIM + k]);
                w = __floats2bfloat162_rn(f.x, f.y);
            }
            sBp[kp][n] = bf2_u32(w);
        }
        __syncthreads();

        __nv_bfloat162 acc2[4][4];
#pragma unroll
        for (int u = 0; u < 4; ++u)
#pragma unroll
            for (int v = 0; v < 4; ++v) acc2[u][v] = zero2;

#pragma unroll
        for (int kp = 0; kp < 16; ++kp) {
            uint4 bv = *reinterpret_cast<const uint4*>(&sBp[kp][tx * 4]);
            uint32_t a0 = sAp[ty * 4 + 0][kp];
            uint32_t a1 = sAp[ty * 4 + 1][kp];
            uint32_t a2 = sAp[ty * 4 + 2][kp];
            uint32_t a3 = sAp[ty * 4 + 3][kp];
            __nv_bfloat162 b0 = u32_bf2(bv.x), b1 = u32_bf2(bv.y);
            __nv_bfloat162 b2 = u32_bf2(bv.z), b3 = u32_bf2(bv.w);
            acc2[0][0] = __hfma2(u32_bf2(a0), b0, acc2[0][0]);
            acc2[0][1] = __hfma2(u32_bf2(a0), b1, acc2[0][1]);
            acc2[0][2] = __hfma2(u32_bf2(a0), b2, acc2[0][2]);
            acc2[0][3] = __hfma2(u32_bf2(a0), b3, acc2[0][3]);
            acc2[1][0] = __hfma2(u32_bf2(a1), b0, acc2[1][0]);
            acc2[1][1] = __hfma2(u32_bf2(a1), b1, acc2[1][1]);
            acc2[1][2] = __hfma2(u32_bf2(a1), b2, acc2[1][2]);
            acc2[1][3] = __hfma2(u32_bf2(a1), b3, acc2[1][3]);
            acc2[2][0] = __hfma2(u32_bf2(a2), b0, acc2[2][0]);
            acc2[2][1] = __hfma2(u32_bf2(a2), b1, acc2[2][1]);
            acc2[2][2] = __hfma2(u32_bf2(a2), b2, acc2[2][2]);
            acc2[2][3] = __hfma2(u32_bf2(a2), b3, acc2[2][3]);
            acc2[3][0] = __hfma2(u32_bf2(a3), b0, acc2[3][0]);
            acc2[3][1] = __hfma2(u32_bf2(a3), b1, acc2[3][1]);
            acc2[3][2] = __hfma2(u32_bf2(a3), b2, acc2[3][2]);
            acc2[3][3] = __hfma2(u32_bf2(a3), b3, acc2[3][3]);
        }
#pragma unroll
        for (int u = 0; u < 4; ++u)
#pragma unroll
            for (int v = 0; v < 4; ++v) {
                float2 p = __bfloat1622float2(acc2[u][v]);
                acc[u][v] += p.x + p.y;
            }
        __syncthreads();
    }
#pragma unroll
    for (int u = 0; u < 4; ++u) {
        int m = m0 + ty * 4 + u;
        size_t base = (size_t)m * SP + n0 + tx * 4;
#pragma unroll
        for (int v = 0; v < 4; v += 2) {
            __nv_bfloat162 p = __floats2bfloat162_rn(acc[u][v], acc[u][v + 1]);
            *reinterpret_cast<uint32_t*>(&g_emis[base + v]) = bf2_u32(p);
        }
    }
}

// ---------------------------------------------------------------------------
// Scan: one CTA per batch, 512 threads (16 warps). Thread (ig = tid>>6,
// jj = tid&63) owns a 20-i-pair x 5-column tile of A, FULLY register-resident
// (25 uint4 = 100 regs) -> zero A loads per step. Per step: 5 broadcast
// LDS.128 of alpha (warp-uniform address), 100 HFMA2 into 5 accumulators
// (20-term bf16 chains), fp32 collapse, coalesced 8-way i-group reduce via
// smem, emission multiply, pair-pack via shfl, 2 barriers. A prescaled by
// 128; renormalize + log-accumulate every 16 steps; ll -= 4095*log(128).
// ---------------------------------------------------------------------------
__global__ void __launch_bounds__(SCAN_THREADS, 1)
scan_kernel(const float* __restrict__ Ivec, float* __restrict__ out) {
    __shared__ uint32_t s_alpha[2][NIP];   // bf16 alpha pairs, double-buffered
    __shared__ float    s_red[8][SP];      // per-i-group partials
    __shared__ float    s_w[16];
    __shared__ float    s_inv;

    const int b    = blockIdx.x;
    const int tid  = threadIdx.x;
    const int ig   = tid >> 6;             // 0..7  (i-pair group of 20)
    const int jj   = tid & 63;             // 0..63
    const int wrp  = tid >> 5;
    const int lane = tid & 31;

    const __nv_bfloat16* erow = g_emis + (size_t)b * T_LEN * SP;
    const uint4* Aq = reinterpret_cast<const uint4*>(g_a);

    // whole A tile register-resident: rA[ql*5 + c], 25 uint4 = 100 regs
    uint4 rA[25];
#pragma unroll
    for (int ql = 0; ql < 5; ++ql)
#pragma unroll
        for (int c = 0; c < 5; ++c)
            rA[ql * 5 + c] = Aq[(((ig * 5 + ql) * 5 + c) * 64) + jj];

    // t = 0: alpha0 = I * e0 (unnormalized, NOT prescaled) into buffer 1
    if (tid < NIP) {
        int j0 = 2 * tid, j1 = j0 + 1;
        float e0 = __bfloat162float(erow[j0]);
        float e1 = __bfloat162float(erow[j1]);
        float w0 = (j0 < S_REAL) ? Ivec[j0] : 0.f;
        float w1 = (j1 < S_REAL) ? Ivec[j1] : 0.f;
        s_alpha[1][tid] = bf2_u32(__floats2bfloat162_rn(w0 * e0, w1 * e1));
    }
    __syncthreads();

    float ll = 0.f;
    float e_cur = 0.f;
    if (tid < SP) e_cur = __bfloat162float(erow[(size_t)SP + tid]);

    const __nv_bfloat162 zero2 = __floats2bfloat162_rn(0.f, 0.f);

    for (int t = 1; t < T_LEN; ++t) {
        const int cur = t & 1;
        float e_next = 0.f;
        if (t + 1 < T_LEN && tid < SP)
            e_next = __bfloat162float(erow[(size_t)(t + 1) * SP + tid]);

        const uint4* al4 = reinterpret_cast<const uint4*>(s_alpha[cur]);

        __nv_bfloat162 a0 = zero2, a1 = zero2, a2 = zero2, a3 = zero2, a4 = zero2;

        // 5 broadcast alpha quads (warp-uniform address), 100 HFMA2 total
#pragma unroll
        for (int ql = 0; ql < 5; ++ql) {
            uint4 av = al4[ig * 5 + ql];
            __nv_bfloat162 x0 = u32_bf2(av.x), x1 = u32_bf2(av.y);
            __nv_bfloat162 x2 = u32_bf2(av.z), x3 = u32_bf2(av.w);
            uint4 w;
            w = rA[ql * 5 + 0];
            a0 = __hfma2(u32_bf2(w.x), x0, a0); a0 = __hfma2(u32_bf2(w.y), x1, a0);
            a0 = __hfma2(u32_bf2(w.z), x2, a0); a0 = __hfma2(u32_bf2(w.w), x3, a0);
            w = rA[ql * 5 + 1];
            a1 = __hfma2(u32_bf2(w.x), x0, a1); a1 = __hfma2(u32_bf2(w.y), x1, a1);
            a1 = __hfma2(u32_bf2(w.z), x2, a1); a1 = __hfma2(u32_bf2(w.w), x3, a1);
            w = rA[ql * 5 + 2];
            a2 = __hfma2(u32_bf2(w.x), x0, a2); a2 = __hfma2(u32_bf2(w.y), x1, a2);
            a2 = __hfma2(u32_bf2(w.z), x2, a2); a2 = __hfma2(u32_bf2(w.w), x3, a2);
            w = rA[ql * 5 + 3];
            a3 = __hfma2(u32_bf2(w.x), x0, a3); a3 = __hfma2(u32_bf2(w.y), x1, a3);
            a3 = __hfma2(u32_bf2(w.z), x2, a3); a3 = __hfma2(u32_bf2(w.w), x3, a3);
            w = rA[ql * 5 + 4];
            a4 = __hfma2(u32_bf2(w.x), x0, a4); a4 = __hfma2(u32_bf2(w.y), x1, a4);
            a4 = __hfma2(u32_bf2(w.z), x2, a4); a4 = __hfma2(u32_bf2(w.w), x3, a4);
        }

        float2 p;
        p = __bfloat1622float2(a0); s_red[ig][jj      ] = p.x + p.y;
        p = __bfloat1622float2(a1); s_red[ig][jj + 64 ] = p.x + p.y;
        p = __bfloat1622float2(a2); s_red[ig][jj + 128] = p.x + p.y;
        p = __bfloat1622float2(a3); s_red[ig][jj + 192] = p.x + p.y;
        p = __bfloat1622float2(a4); s_red[ig][jj + 256] = p.x + p.y;
        __syncthreads();

        float o = 0.f;
        if (tid < SP) {
            o = ((s_red[0][tid] + s_red[1][tid]) + (s_red[2][tid] + s_red[3][tid]))
              + ((s_red[4][tid] + s_red[5][tid]) + (s_red[6][tid] + s_red[7][tid]));
            o *= e_cur;
        }

        if ((t & 15) == 15) {
            // renormalize + accumulate loglik (warps >= 10 contribute 0)
            float s = (tid < SP) ? o : 0.f;
#pragma unroll
            for (int off = 16; off > 0; off >>= 1)
                s += __shfl_xor_sync(0xffffffffu, s, off);
            if (lane == 0) s_w[wrp] = s;
            __syncthreads();
            if (tid == 0) {
                float z = 0.f;
#pragma unroll
                for (int k = 0; k < 10; ++k) z += s_w[k];
                ll += logf(z);
                s_inv = 1.0f / z;
            }
            __syncthreads();
            o *= s_inv;
        }

        // pack (j even, j odd) lane pair; even lane stores the word
        if (tid < SP) {
            float op = __shfl_down_sync(0xffffffffu, o, 1);
            if ((lane & 1) == 0)
                s_alpha[cur ^ 1][tid >> 1] =
                    bf2_u32(__floats2bfloat162_rn(o, op));
        }
        __syncthreads();

        e_cur = e_next;
    }

    // each of the 4095 steps carried an extra factor 128 (folded into A)
    if (tid == 0) out[b] = ll - 4095.0f * logf(128.0f);
}

// ---------------------------------------------------------------------------
extern "C" void kernel_launch(void* const* d_in, const int* in_sizes, int n_in,
                              void* d_out, int out_size) {
    const float* inputs = nullptr;
    const float* A      = nullptr;
    const float* Bm     = nullptr;
    const float* Ivec   = nullptr;
    for (int i = 0; i < n_in; ++i) {
        switch (in_sizes[i]) {
            case NBATCH * T_LEN * E_DIM: inputs = (const float*)d_in[i]; break;
            case S_REAL * S_REAL:        A      = (const float*)d_in[i]; break;
            case S_REAL * E_DIM:         Bm     = (const float*)d_in[i]; break;
            case S_REAL:                 Ivec   = (const float*)d_in[i]; break;
            default: break;
        }
    }
    if (!inputs) inputs = (const float*)d_in[0];
    if (!A)      A      = (const float*)d_in[1];
    if (!Bm)     Bm     = (const float*)d_in[2];
    if (!Ivec)   Ivec   = (const float*)d_in[3];
    float* out = (float*)d_out;

    dim3 ggrid(SP / 64, (NBATCH * T_LEN) / 64);   // (5, 2048)
    prep_gemm_kernel<<<ggrid, 256>>>(inputs, Bm, A);

    scan_kernel<<<NBATCH, SCAN_THREADS>>>(Ivec, out);
    (void)out_size;
}